// round 14
// baseline (speedup 1.0000x reference)
#include <cuda_runtime.h>
#include <cstdint>

// ---------------- problem constants ----------------
#define Bb 8
#define Nn 131072          // F*T
#define Dd 40
#define P  48              // augmented row width (40 E + 4 V + 4 zero)
#define CELLS (P*P)        // 2304
#define CPB 54             // chunks per batch -> 432 CTAs @ 3/SM
#define CHUNK 2432         // 4 groups * 608 rows
#define GROWS 608          // rows per 2-warp group
#define TROWS 32           // rows per tile
#define GT 19              // tiles per group
#define ROWE 160           // E row stride (40 floats) -> conflict-free frags
#define SE_BYTES (TROWS*ROWE)        // 5120
#define SV_BYTES (TROWS*16)          // 512
#define SSTAGE (SE_BYTES+SV_BYTES)   // 5632 B per stage
#define STAGES 3
#define SMEM_BYTES (4*STAGES*SSTAGE) // 67584 B -> 3 CTAs/SM
#define GOFF 6400                    // float offset of G block in smem

// ---------------- device scratch (zero-init; kernel restores zeros) -------
__device__ __align__(16) float g_partials[(size_t)Bb * CPB * CELLS];
__device__ float g_batchval[Bb];
__device__ int g_bdone[Bb];
__device__ int g_done;

// ---------------- PTX helpers ----------------
__device__ __forceinline__ uint32_t smem_u32(const void* p) {
    uint32_t a;
    asm("{ .reg .u64 t; cvta.to.shared.u64 t, %1; cvt.u32.u64 %0, t; }"
        : "=r"(a) : "l"(p));
    return a;
}

#define CVT_TF32(u, f) asm("cvt.rna.tf32.f32 %0, %1;" : "=r"(u) : "f"(f))
#define LDSF(v, a)     asm volatile("ld.shared.f32 %0, [%1];" : "=f"(v) : "r"(a))
#define CPASYNC(dst, src, sz) \
    asm volatile("cp.async.cg.shared.global [%0], [%1], 16, %2;" \
                 :: "r"(dst), "l"(src), "r"(sz) : "memory")
#define CPCOMMIT() asm volatile("cp.async.commit_group;" ::: "memory")
#define CPWAIT2()  asm volatile("cp.async.wait_group 2;" ::: "memory")
#define CPWAIT1()  asm volatile("cp.async.wait_group 1;" ::: "memory")
#define CPWAIT0()  asm volatile("cp.async.wait_group 0;" ::: "memory")
#define BARSYNC64(id) asm volatile("bar.sync %0, 64;" :: "r"(id) : "memory")

// D(16x8) += A(16x8,row) * B(8x8,col), tf32 inputs, f32 accum
#define MMA_TF32(dp, a0, a1, a2, a3, b0, b1) \
    asm volatile("mma.sync.aligned.m16n8k8.row.col.f32.tf32.tf32.f32 " \
        "{%0,%1,%2,%3}, {%4,%5,%6,%7}, {%8,%9}, {%0,%1,%2,%3};" \
        : "+f"((dp)[0]), "+f"((dp)[1]), "+f"((dp)[2]), "+f"((dp)[3]) \
        : "r"(a0), "r"(a1), "r"(a2), "r"(a3), "r"(b0), "r"(b1))

// ---- warp p of a pair stages its half of one 32-row tile ----
__device__ __forceinline__ void stage_half(uint32_t se, uint32_t sv,
                                           const char* __restrict__ Eb,
                                           const char* __restrict__ Vb,
                                           int nrem10, int nrem, int lane, int p)
{
#pragma unroll
    for (int i = 0; i < 5; i++) {
        const int q = i * 64 + p * 32 + lane;
        const bool ok = (q < nrem10);
        const char* src = ok ? (Eb + q * 16) : Eb;
        CPASYNC(se + (uint32_t)(q * 16), src, ok ? 16u : 0u);
    }
    if (p) {
        const bool ok = (lane < nrem);
        const char* src = ok ? (Vb + lane * 16) : Vb;
        CPASYNC(sv + (uint32_t)(lane * 16), src, ok ? 16u : 0u);
    }
    CPCOMMIT();
}

// ============================================================
// Single kernel: per-(batch,chunk) Gram via tf32 HMMA (proven main loop),
// coalesced partials dump, then per-batch LAST-DONE reduction (int
// counters only, fixed-order float sums -> fully deterministic).
// ============================================================
__global__ __launch_bounds__(256, 3)
void gram_fused_kernel(const float* __restrict__ E, const float* __restrict__ V,
                       float* __restrict__ out)
{
    extern __shared__ float sm[];
    const int tid  = threadIdx.x;
    const int w    = tid >> 5;
    const int lane = tid & 31;
    const int g    = lane >> 2;   // 0..7
    const int tig  = lane & 3;    // 0..3
    const int gi   = w >> 1;      // warp-pair group 0..3
    const int p    = w & 1;       // parity within pair
    const int b     = blockIdx.y;
    const int chunk = blockIdx.x;

    const int n_end  = min(Nn, (chunk + 1) * CHUNK);
    const int grp_n0 = chunk * CHUNK + gi * GROWS;
    const int nrem0  = n_end - grp_n0;
    const char* Eb = (const char*)(E + (size_t)b * Nn * Dd) + (size_t)grp_n0 * 160;
    const char* Vb = (const char*)(V + (size_t)b * Nn * 4) + (size_t)grp_n0 * 16;

    const uint32_t sgb = smem_u32(sm) + (uint32_t)(gi * STAGES * SSTAGE);
    const int bar = gi + 1;

#pragma unroll
    for (int s = 0; s < 3; s++)
        stage_half(sgb + s * SSTAGE, sgb + s * SSTAGE + SE_BYTES,
                   Eb + (size_t)s * TROWS * 160, Vb + (size_t)s * TROWS * 16,
                   nrem0 * 10 - s * 320, nrem0 - s * TROWS, lane, p);

    float d[24];
#pragma unroll
    for (int k = 0; k < 24; k++) d[k] = 0.f;

    int buf = 0;
    for (int t = 0; t < GT; t++) {
        const int pend = GT - 1 - t;
        if (pend >= 2)      CPWAIT2();
        else if (pend == 1) CPWAIT1();
        else                CPWAIT0();
        BARSYNC64(bar);            // partner's half landed + fenced

        const uint32_t ce = sgb + (uint32_t)(buf * SSTAGE);
        const uint32_t cv = ce + SE_BYTES;

#pragma unroll
        for (int kk = 0; kk < 4; kk++) {
            const uint32_t ra = ce + (uint32_t)((kk * 8 + tig) * ROWE + g * 4);
            if (p == 0) {          // tiles (0,0)(0,1)(1,0)(1,1)(1,2)(1,3): feats m=0..3
                float f0[4], f1[4]; uint32_t u0[4], u1[4];
#pragma unroll
                for (int m = 0; m < 4; m++) {
                    LDSF(f0[m], ra + m * 32);
                    LDSF(f1[m], ra + 4 * ROWE + m * 32);
                }
#pragma unroll
                for (int m = 0; m < 4; m++) { CVT_TF32(u0[m], f0[m]); CVT_TF32(u1[m], f1[m]); }
                MMA_TF32(&d[0],  u0[0], u0[1], u1[0], u1[1], u0[0], u1[0]);
                MMA_TF32(&d[4],  u0[0], u0[1], u1[0], u1[1], u0[1], u1[1]);
                MMA_TF32(&d[8],  u0[2], u0[3], u1[2], u1[3], u0[0], u1[0]);
                MMA_TF32(&d[12], u0[2], u0[3], u1[2], u1[3], u0[1], u1[1]);
                MMA_TF32(&d[16], u0[2], u0[3], u1[2], u1[3], u0[2], u1[2]);
                MMA_TF32(&d[20], u0[2], u0[3], u1[2], u1[3], u0[3], u1[3]);
            } else {               // tiles (2,0..5): feats m=0..4 from E, m=5 from V(+zeros)
                float f0[5], f1[5]; uint32_t u0[6], u1[6];
#pragma unroll
                for (int m = 0; m < 5; m++) {
                    LDSF(f0[m], ra + m * 32);
                    LDSF(f1[m], ra + 4 * ROWE + m * 32);
                }
                float fv0 = 0.f, fv1 = 0.f;
                if (g < 4) {       // feats 40..43 live; 44..47 structurally zero
                    const uint32_t va = cv + (uint32_t)((kk * 8 + tig) * 16 + g * 4);
                    LDSF(fv0, va);
                    LDSF(fv1, va + 64);   // +4 rows * 16B
                }
#pragma unroll
                for (int m = 0; m < 5; m++) { CVT_TF32(u0[m], f0[m]); CVT_TF32(u1[m], f1[m]); }
                CVT_TF32(u0[5], fv0); CVT_TF32(u1[5], fv1);
                MMA_TF32(&d[0],  u0[4], u0[5], u1[4], u1[5], u0[0], u1[0]);
                MMA_TF32(&d[4],  u0[4], u0[5], u1[4], u1[5], u0[1], u1[1]);
                MMA_TF32(&d[8],  u0[4], u0[5], u1[4], u1[5], u0[2], u1[2]);
                MMA_TF32(&d[12], u0[4], u0[5], u1[4], u1[5], u0[3], u1[3]);
                MMA_TF32(&d[16], u0[4], u0[5], u1[4], u1[5], u0[4], u1[4]);
                MMA_TF32(&d[20], u0[4], u0[5], u1[4], u1[5], u0[5], u1[5]);
            }
        }
        BARSYNC64(bar);            // both warps done reading before overwrite

        if (t + 3 < GT)
            stage_half(ce, cv,
                       Eb + (size_t)(t + 3) * TROWS * 160,
                       Vb + (size_t)(t + 3) * TROWS * 16,
                       nrem0 * 10 - (t + 3) * 320, nrem0 - (t + 3) * TROWS, lane, p);

        buf = (buf == 2) ? 0 : buf + 1;
    }

    CPWAIT0();

    // ---- fold 4 groups ----
    __syncthreads();
    {
        float* dst = sm + (size_t)(w * 32 + lane) * 25;   // odd stride
#pragma unroll
        for (int k = 0; k < 24; k++) dst[k] = d[k];
    }
    __syncthreads();

    float* G = sm + GOFF;
    if (w < 2) {
        const float* fold = sm;
#pragma unroll
        for (int k = 0; k < 24; k++) {
            float s = 0.f;
#pragma unroll
            for (int e = 0; e < 4; e++)
                s += fold[(size_t)(((w + 2 * e) * 32) + lane) * 25 + k];
            d[k] = s;
        }
        const int MT0[6] = {0,0,1,1,1,1};
        const int NT0[6] = {0,1,0,1,2,3};
#pragma unroll
        for (int f = 0; f < 6; f++) {
            const int i0 = (w == 0) ? (16 * MT0[f] + g) : (32 + g);
            const int j0 = ((w == 0) ? (8 * NT0[f]) : (8 * f)) + 2 * tig;
#pragma unroll
            for (int h = 0; h < 2; h++) {
                const int ii = i0 + 8 * h;
#pragma unroll
                for (int e = 0; e < 2; e++) {
                    const float v = d[f * 4 + 2 * h + e];
                    const int jj = j0 + e;
                    G[ii * P + jj] = v;
                    G[jj * P + ii] = v;   // mirror (overlap writes same value)
                }
            }
        }
    }
    __syncthreads();

    // coalesced dump: one contiguous 9.2KB block per CTA
    {
        float4* out4 = (float4*)&g_partials[(size_t)(b * CPB + chunk) * CELLS];
        const float4* G4 = (const float4*)G;
#pragma unroll
        for (int i = tid; i < CELLS / 4; i += 256)
            out4[i] = G4[i];
    }

    // ==== per-batch last-done reduction (int counters, no float atomics) ====
    __threadfence();
    __shared__ int slast;
    if (tid == 0)
        slast = (atomicAdd(&g_bdone[b], 1) == CPB - 1) ? 1 : 0;
    __syncthreads();
    if (!slast) return;
    __threadfence();                       // acquire: all 54 dumps visible
    if (tid == 0) g_bdone[b] = 0;          // restore counter invariant

    // reduce batch b: 576 float4 columns x 54 chunks (L2-resident, coalesced)
    const float4* base4 = (const float4*)&g_partials[(size_t)b * CPB * CELLS];
    float acc = 0.f;
#pragma unroll 1
    for (int c4 = tid; c4 < CELLS / 4; c4 += 256) {
        float4 a0 = make_float4(0.f,0.f,0.f,0.f), a1 = a0, a2 = a0;
        float4 a3 = a0, a4 = a0, a5 = a0;
#pragma unroll 1
        for (int c = 0; c < CPB; c += 6) {         // 54 = 9*6, fixed order
            const float4 v0 = base4[(size_t)(c+0) * (CELLS/4) + c4];
            const float4 v1 = base4[(size_t)(c+1) * (CELLS/4) + c4];
            const float4 v2 = base4[(size_t)(c+2) * (CELLS/4) + c4];
            const float4 v3 = base4[(size_t)(c+3) * (CELLS/4) + c4];
            const float4 v4 = base4[(size_t)(c+4) * (CELLS/4) + c4];
            const float4 v5 = base4[(size_t)(c+5) * (CELLS/4) + c4];
            a0.x+=v0.x; a0.y+=v0.y; a0.z+=v0.z; a0.w+=v0.w;
            a1.x+=v1.x; a1.y+=v1.y; a1.z+=v1.z; a1.w+=v1.w;
            a2.x+=v2.x; a2.y+=v2.y; a2.z+=v2.z; a2.w+=v2.w;
            a3.x+=v3.x; a3.y+=v3.y; a3.z+=v3.z; a3.w+=v3.w;
            a4.x+=v4.x; a4.y+=v4.y; a4.z+=v4.z; a4.w+=v4.w;
            a5.x+=v5.x; a5.y+=v5.y; a5.z+=v5.z; a5.w+=v5.w;
        }
        float4 s4;
        s4.x = ((a0.x+a1.x)+(a2.x+a3.x))+(a4.x+a5.x);
        s4.y = ((a0.y+a1.y)+(a2.y+a3.y))+(a4.y+a5.y);
        s4.z = ((a0.z+a1.z)+(a2.z+a3.z))+(a4.z+a5.z);
        s4.w = ((a0.w+a1.w)+(a2.w+a3.w))+(a4.w+a5.w);
        // weight: uniform within a float4 (j0 = (c4%12)*4, 40 % 4 == 0)
        const int i2 = c4 / 12;
        const int j0 = (c4 - i2 * 12) * 4;
        const float wgt = ((i2 < Dd) == (j0 < Dd)) ? 1.0f : -1.0f;
        acc += wgt * ((s4.x*s4.x + s4.y*s4.y) + (s4.z*s4.z + s4.w*s4.w));
    }

    __syncthreads();                       // smem free for reuse
    float* red = sm;
    red[tid] = acc;
    __syncthreads();
#pragma unroll
    for (int h = 128; h > 0; h >>= 1) {
        if (tid < h) red[tid] += red[tid + h];
        __syncthreads();
    }

    __shared__ int sfin;
    if (tid == 0) {
        g_batchval[b] = red[0];
        __threadfence();
        sfin = (atomicAdd(&g_done, 1) == Bb - 1) ? 1 : 0;
    }
    __syncthreads();
    if (!sfin) return;

    if (tid == 0) {
        __threadfence();                   // acquire all batch values
        float tot = 0.f;
#pragma unroll
        for (int e = 0; e < Bb; e++) tot += g_batchval[e];   // fixed order
        out[0] = tot * (1.0f / (float)((size_t)Bb * Nn));
        g_done = 0;                        // restore counter invariant
    }
}

// ============================================================
extern "C" void kernel_launch(void* const* d_in, const int* in_sizes, int n_in,
                              void* d_out, int out_size)
{
    const float* E = (const float*)d_in[0];
    const float* V = (const float*)d_in[1];
    if (n_in >= 2 && in_sizes[0] < in_sizes[1]) {
        const float* tmp = E; E = V; V = tmp;
    }

    cudaFuncSetAttribute(gram_fused_kernel,
                         cudaFuncAttributeMaxDynamicSharedMemorySize, SMEM_BYTES);

    dim3 grid1(CPB, Bb);
    gram_fused_kernel<<<grid1, 256, SMEM_BYTES>>>(E, V, (float*)d_out);
}

// round 15
// speedup vs baseline: 1.5073x; 1.5073x over previous
#include <cuda_runtime.h>
#include <cstdint>

// ---------------- problem constants ----------------
#define Bb 8
#define Nn 131072          // F*T
#define Dd 40
#define P  48              // augmented row width (40 E + 4 V + 4 zero)
#define CELLS (P*P)        // 2304
#define CPB 54             // chunks per batch -> 432 CTAs
#define CHUNK 2432         // 4 groups * 608 rows
#define GROWS 608          // rows per 2-warp group
#define TROWS 32           // rows per tile
#define GT 19              // tiles per group
#define ROWE 160           // E row stride (40 floats) -> conflict-free frags
#define SE_BYTES (TROWS*ROWE)        // 5120
#define SV_BYTES (TROWS*16)          // 512
#define SSTAGE (SE_BYTES+SV_BYTES)   // 5632 B per stage
#define STAGES 2
#define SMEM_BYTES (4*STAGES*SSTAGE) // 45056 B -> 4 CTAs/SM (180KB)
#define GOFF 6400                    // float offset of G block in smem
#define R_BLOCKS 576                 // reduce blocks: 18432 elems / 32 per block

// ---------------- device scratch ----------------
// layout: g_partials[(b*CPB + chunk)*CELLS + cell]  -- contiguous per-CTA block
__device__ __align__(16) float g_partials[(size_t)Bb * CPB * CELLS];
__device__ float g_blocksums[R_BLOCKS];
__device__ int g_done;   // zero-initialized; kernel restores zero each run

// ---------------- PTX helpers ----------------
__device__ __forceinline__ uint32_t smem_u32(const void* p) {
    uint32_t a;
    asm("{ .reg .u64 t; cvta.to.shared.u64 t, %1; cvt.u32.u64 %0, t; }"
        : "=r"(a) : "l"(p));
    return a;
}

#define CVT_TF32(u, f) asm("cvt.rna.tf32.f32 %0, %1;" : "=r"(u) : "f"(f))
#define LDSF(v, a)     asm volatile("ld.shared.f32 %0, [%1];" : "=f"(v) : "r"(a))
#define CPASYNC(dst, src, sz) \
    asm volatile("cp.async.cg.shared.global [%0], [%1], 16, %2;" \
                 :: "r"(dst), "l"(src), "r"(sz) : "memory")
#define CPCOMMIT() asm volatile("cp.async.commit_group;" ::: "memory")
#define CPWAIT1()  asm volatile("cp.async.wait_group 1;" ::: "memory")
#define CPWAIT0()  asm volatile("cp.async.wait_group 0;" ::: "memory")
#define BARSYNC64(id) asm volatile("bar.sync %0, 64;" :: "r"(id) : "memory")

// D(16x8) += A(16x8,row) * B(8x8,col), tf32 inputs, f32 accum
#define MMA_TF32(dp, a0, a1, a2, a3, b0, b1) \
    asm volatile("mma.sync.aligned.m16n8k8.row.col.f32.tf32.tf32.f32 " \
        "{%0,%1,%2,%3}, {%4,%5,%6,%7}, {%8,%9}, {%0,%1,%2,%3};" \
        : "+f"((dp)[0]), "+f"((dp)[1]), "+f"((dp)[2]), "+f"((dp)[3]) \
        : "r"(a0), "r"(a1), "r"(a2), "r"(a3), "r"(b0), "r"(b1))

// ---- warp p of a pair stages its half of one 32-row tile ----
__device__ __forceinline__ void stage_half(uint32_t se, uint32_t sv,
                                           const char* __restrict__ Eb,
                                           const char* __restrict__ Vb,
                                           int nrem10, int nrem, int lane, int p)
{
#pragma unroll
    for (int i = 0; i < 5; i++) {
        const int q = i * 64 + p * 32 + lane;
        const bool ok = (q < nrem10);
        const char* src = ok ? (Eb + q * 16) : Eb;
        CPASYNC(se + (uint32_t)(q * 16), src, ok ? 16u : 0u);
    }
    if (p) {
        const bool ok = (lane < nrem);
        const char* src = ok ? (Vb + lane * 16) : Vb;
        CPASYNC(sv + (uint32_t)(lane * 16), src, ok ? 16u : 0u);
    }
    CPCOMMIT();
}

// ============================================================
// Kernel 1: partial Gram G = X^T X per (batch, chunk), tf32 HMMA.
// Warp pairs, double-buffered compact slab, 4 CTAs/SM for issue width.
// Epilogue assembles FULL symmetric G in smem, dumps one coalesced block.
// ============================================================
__global__ __launch_bounds__(256, 4)
void gram_hmma_kernel(const float* __restrict__ E, const float* __restrict__ V)
{
    extern __shared__ float sm[];
    const int tid  = threadIdx.x;
    const int w    = tid >> 5;
    const int lane = tid & 31;
    const int g    = lane >> 2;   // 0..7
    const int tig  = lane & 3;    // 0..3
    const int gi   = w >> 1;      // warp-pair group 0..3
    const int p    = w & 1;       // parity within pair
    const int b     = blockIdx.y;
    const int chunk = blockIdx.x;

    const int n_end  = min(Nn, (chunk + 1) * CHUNK);
    const int grp_n0 = chunk * CHUNK + gi * GROWS;
    const int nrem0  = n_end - grp_n0;
    const char* Eb = (const char*)(E + (size_t)b * Nn * Dd) + (size_t)grp_n0 * 160;
    const char* Vb = (const char*)(V + (size_t)b * Nn * 4) + (size_t)grp_n0 * 16;

    const uint32_t sgb = smem_u32(sm) + (uint32_t)(gi * STAGES * SSTAGE);
    const int bar = gi + 1;

    // prologue: stage tiles 0,1 (no zero-init; every read byte is
    // cp.async-written each stage, incl. zero-fill tails)
#pragma unroll
    for (int s = 0; s < 2; s++)
        stage_half(sgb + s * SSTAGE, sgb + s * SSTAGE + SE_BYTES,
                   Eb + (size_t)s * TROWS * 160, Vb + (size_t)s * TROWS * 16,
                   nrem0 * 10 - s * 320, nrem0 - s * TROWS, lane, p);

    float d[24];
#pragma unroll
    for (int k = 0; k < 24; k++) d[k] = 0.f;

    for (int t = 0; t < GT; t++) {
        if (t + 1 < GT) CPWAIT1();
        else            CPWAIT0();
        BARSYNC64(bar);            // partner's half landed + fenced

        const uint32_t ce = sgb + (uint32_t)((t & 1) * SSTAGE);
        const uint32_t cv = ce + SE_BYTES;

#pragma unroll
        for (int kk = 0; kk < 4; kk++) {
            const uint32_t ra = ce + (uint32_t)((kk * 8 + tig) * ROWE + g * 4);
            if (p == 0) {          // tiles (0,0)(0,1)(1,0)(1,1)(1,2)(1,3): feats m=0..3
                float f0[4], f1[4]; uint32_t u0[4], u1[4];
#pragma unroll
                for (int m = 0; m < 4; m++) {
                    LDSF(f0[m], ra + m * 32);
                    LDSF(f1[m], ra + 4 * ROWE + m * 32);
                }
#pragma unroll
                for (int m = 0; m < 4; m++) { CVT_TF32(u0[m], f0[m]); CVT_TF32(u1[m], f1[m]); }
                MMA_TF32(&d[0],  u0[0], u0[1], u1[0], u1[1], u0[0], u1[0]);
                MMA_TF32(&d[4],  u0[0], u0[1], u1[0], u1[1], u0[1], u1[1]);
                MMA_TF32(&d[8],  u0[2], u0[3], u1[2], u1[3], u0[0], u1[0]);
                MMA_TF32(&d[12], u0[2], u0[3], u1[2], u1[3], u0[1], u1[1]);
                MMA_TF32(&d[16], u0[2], u0[3], u1[2], u1[3], u0[2], u1[2]);
                MMA_TF32(&d[20], u0[2], u0[3], u1[2], u1[3], u0[3], u1[3]);
            } else {               // tiles (2,0..5): feats m=0..4 from E, m=5 from V(+zeros)
                float f0[5], f1[5]; uint32_t u0[6], u1[6];
#pragma unroll
                for (int m = 0; m < 5; m++) {
                    LDSF(f0[m], ra + m * 32);
                    LDSF(f1[m], ra + 4 * ROWE + m * 32);
                }
                float fv0 = 0.f, fv1 = 0.f;
                if (g < 4) {       // feats 40..43 live; 44..47 structurally zero
                    const uint32_t va = cv + (uint32_t)((kk * 8 + tig) * 16 + g * 4);
                    LDSF(fv0, va);
                    LDSF(fv1, va + 64);   // +4 rows * 16B
                }
#pragma unroll
                for (int m = 0; m < 5; m++) { CVT_TF32(u0[m], f0[m]); CVT_TF32(u1[m], f1[m]); }
                CVT_TF32(u0[5], fv0); CVT_TF32(u1[5], fv1);
                MMA_TF32(&d[0],  u0[4], u0[5], u1[4], u1[5], u0[0], u1[0]);
                MMA_TF32(&d[4],  u0[4], u0[5], u1[4], u1[5], u0[1], u1[1]);
                MMA_TF32(&d[8],  u0[4], u0[5], u1[4], u1[5], u0[2], u1[2]);
                MMA_TF32(&d[12], u0[4], u0[5], u1[4], u1[5], u0[3], u1[3]);
                MMA_TF32(&d[16], u0[4], u0[5], u1[4], u1[5], u0[4], u1[4]);
                MMA_TF32(&d[20], u0[4], u0[5], u1[4], u1[5], u0[5], u1[5]);
            }
        }
        BARSYNC64(bar);            // both warps done reading before overwrite

        if (t + 2 < GT)
            stage_half(ce, cv,
                       Eb + (size_t)(t + 2) * TROWS * 160,
                       Vb + (size_t)(t + 2) * TROWS * 16,
                       nrem0 * 10 - (t + 2) * 320, nrem0 - (t + 2) * TROWS, lane, p);
    }

    CPWAIT0();

    // ---- fold 4 groups ----
    __syncthreads();
    {
        float* dst = sm + (size_t)(w * 32 + lane) * 25;   // odd stride
#pragma unroll
        for (int k = 0; k < 24; k++) dst[k] = d[k];
    }
    __syncthreads();

    float* G = sm + GOFF;
    if (w < 2) {
        const float* fold = sm;
#pragma unroll
        for (int k = 0; k < 24; k++) {
            float s = 0.f;
#pragma unroll
            for (int e = 0; e < 4; e++)
                s += fold[(size_t)(((w + 2 * e) * 32) + lane) * 25 + k];
            d[k] = s;
        }
        const int MT0[6] = {0,0,1,1,1,1};
        const int NT0[6] = {0,1,0,1,2,3};
#pragma unroll
        for (int f = 0; f < 6; f++) {
            const int i0 = (w == 0) ? (16 * MT0[f] + g) : (32 + g);
            const int j0 = ((w == 0) ? (8 * NT0[f]) : (8 * f)) + 2 * tig;
#pragma unroll
            for (int h = 0; h < 2; h++) {
                const int ii = i0 + 8 * h;
#pragma unroll
                for (int e = 0; e < 2; e++) {
                    const float v = d[f * 4 + 2 * h + e];
                    const int jj = j0 + e;
                    G[ii * P + jj] = v;
                    G[jj * P + ii] = v;   // mirror (overlap writes same value)
                }
            }
        }
    }
    __syncthreads();

    // coalesced dump: one contiguous 9.2KB block per CTA
    {
        float4* out4 = (float4*)&g_partials[(size_t)(b * CPB + chunk) * CELLS];
        const float4* G4 = (const float4*)G;
#pragma unroll
        for (int i = tid; i < CELLS / 4; i += 256)
            out4[i] = G4[i];
    }
}

// ============================================================
// Kernel 2 (parallel fused reduce, proven 6.75us): 576 blocks as
// 8 chunk-lanes x 32 cell-lanes; last-done block makes the
// deterministic fixed-order final sum. No float atomics anywhere.
// ============================================================
__global__ __launch_bounds__(256)
void reduce_fused_kernel(float* __restrict__ out)
{
    const int tid = threadIdx.x;
    const int cr  = tid >> 5;                 // chunk lane 0..7
    const int cl  = tid & 31;                 // cell lane 0..31
    const int idx = blockIdx.x * 32 + cl;     // (b*CELLS + cell)
    const int b    = idx / CELLS;             // 32-elem block never crosses b
    const int cell = idx - b * CELLS;

    const float* p = &g_partials[(size_t)b * CPB * CELLS + cell];
    float s = 0.f;
#pragma unroll
    for (int k = 0; k < 7; k++) {
        const int c = cr + 8 * k;
        if (c < CPB) s += p[(size_t)c * CELLS];
    }

    __shared__ float red[8 * 33];
    red[cr * 33 + cl] = s;
    __syncthreads();

    if (cr < 4) red[cr * 33 + cl] += red[(cr + 4) * 33 + cl];
    __syncthreads();
    if (cr < 2) red[cr * 33 + cl] += red[(cr + 2) * 33 + cl];
    __syncthreads();

    __shared__ float bsum;
    if (cr == 0) {
        const float st = red[cl] + red[33 + cl];
        const int i = cell / P;
        const int j = cell - i * P;
        const float wgt = ((i < Dd) == (j < Dd)) ? 1.0f : -1.0f;
        float v = wgt * st * st;
#pragma unroll
        for (int h = 16; h > 0; h >>= 1)
            v += __shfl_xor_sync(0xffffffffu, v, h);
        if (cl == 0) bsum = v;
    }
    __syncthreads();

    __shared__ int slast;
    if (tid == 0) {
        g_blocksums[blockIdx.x] = bsum;
        __threadfence();
        slast = (atomicAdd(&g_done, 1) == R_BLOCKS - 1) ? 1 : 0;
    }
    __syncthreads();
    if (!slast) return;

    float acc = 0.f;
#pragma unroll
    for (int t2 = tid; t2 < R_BLOCKS; t2 += 256)
        acc += g_blocksums[t2];
    __shared__ float fin[256];
    fin[tid] = acc;
    __syncthreads();
#pragma unroll
    for (int h = 128; h > 0; h >>= 1) {
        if (tid < h) fin[tid] += fin[tid + h];
        __syncthreads();
    }
    if (tid == 0) {
        out[0] = fin[0] * (1.0f / (float)((size_t)Bb * Nn));
        g_done = 0;                    // restore counter invariant
    }
}

// ============================================================
extern "C" void kernel_launch(void* const* d_in, const int* in_sizes, int n_in,
                              void* d_out, int out_size)
{
    const float* E = (const float*)d_in[0];
    const float* V = (const float*)d_in[1];
    if (n_in >= 2 && in_sizes[0] < in_sizes[1]) {
        const float* tmp = E; E = V; V = tmp;
    }

    cudaFuncSetAttribute(gram_hmma_kernel,
                         cudaFuncAttributeMaxDynamicSharedMemorySize, SMEM_BYTES);

    dim3 grid1(CPB, Bb);
    gram_hmma_kernel<<<grid1, 256, SMEM_BYTES>>>(E, V);
    reduce_fused_kernel<<<R_BLOCKS, 256>>>((float*)d_out);
}